// round 7
// baseline (speedup 1.0000x reference)
#include <cuda_runtime.h>
#include <cuda_fp16.h>

#define B_  131072
#define DD  784
#define HID 256
#define MD  16
#define RS  80   // padded smem row stride (bytes) for a 32-half k-row

__device__ __align__(16) __half g_W1t_hi[HID * 832];
__device__ __align__(16) __half g_W1t_lo[HID * 832];
__device__ __align__(16) __half g_W2t_hi[HID * HID];
__device__ __align__(16) __half g_W2t_lo[HID * HID];
__device__ __align__(16) __half g_Wpt_hi[MD * 832];
__device__ __align__(16) __half g_Wpt_lo[MD * 832];
__device__ __align__(16) __half g_h_hi[(size_t)B_ * HID];
__device__ __align__(16) __half g_h_lo[(size_t)B_ * HID];
__device__ __align__(16) float g_gf[(size_t)B_ * HID];
__device__ __align__(16) float g_xi[(size_t)B_ * MD];

__device__ __forceinline__ unsigned su32(const void* p) {
    unsigned a;
    asm("{ .reg .u64 t; cvta.to.shared.u64 t, %1; cvt.u32.u64 %0, t; }" : "=r"(a) : "l"(p));
    return a;
}
__device__ __forceinline__ void ldm4(unsigned (&r)[4], unsigned addr) {
    asm volatile("ldmatrix.sync.aligned.m8n8.x4.shared.b16 {%0,%1,%2,%3}, [%4];"
                 : "=r"(r[0]), "=r"(r[1]), "=r"(r[2]), "=r"(r[3]) : "r"(addr));
}
__device__ __forceinline__ void mma16816(float (&c)[4], const unsigned (&a)[4],
                                         unsigned b0, unsigned b1) {
    asm volatile("mma.sync.aligned.m16n8k16.row.col.f32.f16.f16.f32 "
                 "{%0,%1,%2,%3}, {%4,%5,%6,%7}, {%8,%9}, {%0,%1,%2,%3};"
                 : "+f"(c[0]), "+f"(c[1]), "+f"(c[2]), "+f"(c[3])
                 : "r"(a[0]), "r"(a[1]), "r"(a[2]), "r"(a[3]), "r"(b0), "r"(b1));
}
__device__ __forceinline__ void cpa16(unsigned s, const void* g) {
    asm volatile("cp.async.cg.shared.global [%0], [%1], 16;" :: "r"(s), "l"(g));
}
#define CP_COMMIT() asm volatile("cp.async.commit_group;" ::: "memory")
#define CP_WAIT0()  asm volatile("cp.async.wait_group 0;" ::: "memory")

__device__ __forceinline__ unsigned pk(__half a, __half b) {
    return (unsigned)__half_as_ushort(a) | ((unsigned)__half_as_ushort(b) << 16);
}
__device__ __forceinline__ void split(float v, __half& h, __half& l) {
    h = __float2half_rn(v);
    l = __float2half_rn(v - __half2float(h));
}

// prep: plain transposed row-major [n][k] fp16 hi/lo, zero-padded K
__global__ void prep_kernel(const float* __restrict__ W1, const float* __restrict__ W2,
                            const float* __restrict__ Wp) {
    int idx = blockIdx.x * 256 + threadIdx.x;
    const int T1 = HID * 832, T2 = HID * HID, T3 = MD * 832;
    if (idx < T1) {
        int n = idx / 832, k = idx - n * 832;
        float v = (k < DD) ? W1[(size_t)k * HID + n] : 0.0f;
        __half h, l; split(v, h, l);
        g_W1t_hi[idx] = h; g_W1t_lo[idx] = l;
    } else if (idx < T1 + T2) {
        int j = idx - T1, n = j >> 8, k = j & 255;
        float v = W2[(size_t)k * HID + n];
        __half h, l; split(v, h, l);
        g_W2t_hi[j] = h; g_W2t_lo[j] = l;
    } else if (idx < T1 + T2 + T3) {
        int j = idx - T1 - T2, n = j / 832, k = j - n * 832;
        float v = (k < DD) ? Wp[(size_t)k * MD + n] : 0.0f;
        __half h, l; split(v, h, l);
        g_Wpt_hi[j] = h; g_Wpt_lo[j] = l;
    }
}

// smem layout per stage (51200 B): A hi 5120 | A lo 5120 | B hi 20480 | B lo 20480
#define AHI(s) ((s) * 51200)
#define ALO(s) ((s) * 51200 + 5120)
#define BHI(s) ((s) * 51200 + 10240)
#define BLO(s) ((s) * 51200 + 30720)
#define PHI(s) (102400 + (s) * 2560)
#define PLO(s) (102400 + (s) * 2560 + 1280)
#define SMG1 107520
#define SMG2 102400

// ---------- GEMM1 merged: h = relu(x@W1+b1), xi = x@Wp+bp. M64 N256 k32 -----
__global__ __launch_bounds__(256, 2)
void gemm1_m(const float* __restrict__ X, const float* __restrict__ b1v,
             const float* __restrict__ bpv) {
    extern __shared__ char smc[];
    const unsigned sb = su32(smc);
    const int tid = threadIdx.x, lane = tid & 31, w = tid >> 5;
    const int wm = w >> 2, wn = w & 3;
    const int t8 = lane >> 3, r8 = lane & 7;
    const size_t row0 = (size_t)blockIdx.x * 64;

    float acc[2][8][4] = {};
    float axi[2][2][4] = {};
    float xr[8];
    const int ar = tid >> 2, av = tid & 3;

    auto ldgA = [&](int c) {
        int col = c * 32 + av * 8;
        if (col < DD) {
            *(float4*)xr       = *(const float4*)(X + (row0 + ar) * DD + col);
            *(float4*)(xr + 4) = *(const float4*)(X + (row0 + ar) * DD + col + 4);
        } else {
#pragma unroll
            for (int i = 0; i < 8; i++) xr[i] = 0.0f;
        }
    };
    auto stsA = [&](int s) {
        __half h[8], l[8];
#pragma unroll
        for (int i = 0; i < 8; i++) split(xr[i], h[i], l[i]);
        uint4 vh, vl;
        vh.x = pk(h[0], h[1]); vh.y = pk(h[2], h[3]); vh.z = pk(h[4], h[5]); vh.w = pk(h[6], h[7]);
        vl.x = pk(l[0], l[1]); vl.y = pk(l[2], l[3]); vl.z = pk(l[4], l[5]); vl.w = pk(l[6], l[7]);
        *(uint4*)(smc + AHI(s) + ar * RS + av * 16) = vh;
        *(uint4*)(smc + ALO(s) + ar * RS + av * 16) = vl;
    };
    auto cpaB = [&](int c, int s) {
#pragma unroll
        for (int i = 0; i < 4; i++) {
            int j = tid + i * 256, r = j >> 2, v = j & 3;
            const size_t src = (size_t)r * 832 + c * 32 + v * 8;
            cpa16(sb + BHI(s) + r * RS + v * 16, g_W1t_hi + src);
            cpa16(sb + BLO(s) + r * RS + v * 16, g_W1t_lo + src);
        }
        if (tid < 128) {
            int r = (tid & 63) >> 2, v = tid & 3;
            const size_t src = (size_t)r * 832 + c * 32 + v * 8;
            if (tid < 64) cpa16(sb + PHI(s) + r * RS + v * 16, g_Wpt_hi + src);
            else          cpa16(sb + PLO(s) + r * RS + v * 16, g_Wpt_lo + src);
        }
    };

    ldgA(0); stsA(0); cpaB(0, 0);
    CP_COMMIT(); CP_WAIT0();
    __syncthreads();

    for (int c = 0; c < 26; c++) {
        const int s = c & 1;
        const bool more = (c + 1 < 26);
        if (more) { ldgA(c + 1); cpaB(c + 1, s ^ 1); CP_COMMIT(); }
#pragma unroll
        for (int ks = 0; ks < 2; ks++) {
            const int u = ks * 2 + (t8 >> 1);
            unsigned ah[2][4], al[2][4];
#pragma unroll
            for (int mi = 0; mi < 2; mi++) {
                int m = wm * 32 + mi * 16 + (t8 & 1) * 8 + r8;
                ldm4(ah[mi], sb + AHI(s) + m * RS + u * 16);
                ldm4(al[mi], sb + ALO(s) + m * RS + u * 16);
            }
#pragma unroll
            for (int ng = 0; ng < 4; ng++) {
                unsigned bh[4], bo[4];
                int n = wn * 64 + ng * 16 + (t8 & 1) * 8 + r8;
                ldm4(bh, sb + BHI(s) + n * RS + u * 16);
                ldm4(bo, sb + BLO(s) + n * RS + u * 16);
#pragma unroll
                for (int mi = 0; mi < 2; mi++)
#pragma unroll
                    for (int o = 0; o < 2; o++) {
                        float (&A_)[4] = acc[mi][ng * 2 + o];
                        mma16816(A_, ah[mi], bh[o], bh[o + 2]);
                        mma16816(A_, ah[mi], bo[o], bo[o + 2]);
                        mma16816(A_, al[mi], bh[o], bh[o + 2]);
                    }
            }
            if (wn == 0) {
                unsigned ph[4], po[4];
                int n = (t8 & 1) * 8 + r8;
                ldm4(ph, sb + PHI(s) + n * RS + u * 16);
                ldm4(po, sb + PLO(s) + n * RS + u * 16);
#pragma unroll
                for (int mi = 0; mi < 2; mi++)
#pragma unroll
                    for (int nj = 0; nj < 2; nj++) {
                        mma16816(axi[mi][nj], ah[mi], ph[nj], ph[nj + 2]);
                        mma16816(axi[mi][nj], ah[mi], po[nj], po[nj + 2]);
                        mma16816(axi[mi][nj], al[mi], ph[nj], ph[nj + 2]);
                    }
            }
        }
        if (more) stsA(s ^ 1);
        CP_WAIT0();
        __syncthreads();
    }

    const int rq = lane >> 2, cq = (lane & 3) * 2;
#pragma unroll
    for (int mi = 0; mi < 2; mi++)
#pragma unroll
        for (int nj = 0; nj < 8; nj++) {
            const int colg = wn * 64 + nj * 8 + cq;
            const float bb0 = __ldg(b1v + colg), bb1 = __ldg(b1v + colg + 1);
#pragma unroll
            for (int hr = 0; hr < 2; hr++) {
                const int r = wm * 32 + mi * 16 + rq + hr * 8;
                float v0 = fmaxf(acc[mi][nj][hr * 2 + 0] + bb0, 0.0f);
                float v1 = fmaxf(acc[mi][nj][hr * 2 + 1] + bb1, 0.0f);
                __half h0, l0, h1, l1;
                split(v0, h0, l0); split(v1, h1, l1);
                const size_t gi = (row0 + r) * HID + colg;
                *(unsigned*)(g_h_hi + gi) = pk(h0, h1);
                *(unsigned*)(g_h_lo + gi) = pk(l0, l1);
            }
        }
    if (wn == 0) {
#pragma unroll
        for (int mi = 0; mi < 2; mi++)
#pragma unroll
            for (int nj = 0; nj < 2; nj++) {
                const int colg = nj * 8 + cq;
                const float bb0 = __ldg(bpv + colg), bb1 = __ldg(bpv + colg + 1);
#pragma unroll
                for (int hr = 0; hr < 2; hr++) {
                    const int r = wm * 32 + mi * 16 + rq + hr * 8;
                    float2 v = make_float2(axi[mi][nj][hr * 2 + 0] + bb0,
                                           axi[mi][nj][hr * 2 + 1] + bb1);
                    *(float2*)(g_xi + (row0 + r) * MD + colg) = v;
                }
            }
    }
}

// ---------- GEMM2 merged: gf = h@W2+b2. M64 N256 k32 -----------------------
__global__ __launch_bounds__(256, 2)
void gemm2_m(const float* __restrict__ b2v) {
    extern __shared__ char smc[];
    const unsigned sb = su32(smc);
    const int tid = threadIdx.x, lane = tid & 31, w = tid >> 5;
    const int wm = w >> 2, wn = w & 3;
    const int t8 = lane >> 3, r8 = lane & 7;
    const size_t row0 = (size_t)blockIdx.x * 64;

    float acc[2][8][4] = {};

    auto cpaA = [&](int c, int s) {
        int r = tid >> 2, v = tid & 3;
        const size_t src = (row0 + r) * HID + c * 32 + v * 8;
        cpa16(sb + AHI(s) + r * RS + v * 16, g_h_hi + src);
        cpa16(sb + ALO(s) + r * RS + v * 16, g_h_lo + src);
    };
    auto cpaB = [&](int c, int s) {
#pragma unroll
        for (int i = 0; i < 4; i++) {
            int j = tid + i * 256, r = j >> 2, v = j & 3;
            const size_t src = (size_t)r * HID + c * 32 + v * 8;
            cpa16(sb + BHI(s) + r * RS + v * 16, g_W2t_hi + src);
            cpa16(sb + BLO(s) + r * RS + v * 16, g_W2t_lo + src);
        }
    };

    cpaA(0, 0); cpaB(0, 0);
    CP_COMMIT(); CP_WAIT0();
    __syncthreads();

    for (int c = 0; c < 8; c++) {
        const int s = c & 1;
        const bool more = (c + 1 < 8);
        if (more) { cpaA(c + 1, s ^ 1); cpaB(c + 1, s ^ 1); CP_COMMIT(); }
#pragma unroll
        for (int ks = 0; ks < 2; ks++) {
            const int u = ks * 2 + (t8 >> 1);
            unsigned ah[2][4], al[2][4];
#pragma unroll
            for (int mi = 0; mi < 2; mi++) {
                int m = wm * 32 + mi * 16 + (t8 & 1) * 8 + r8;
                ldm4(ah[mi], sb + AHI(s) + m * RS + u * 16);
                ldm4(al[mi], sb + ALO(s) + m * RS + u * 16);
            }
#pragma unroll
            for (int ng = 0; ng < 4; ng++) {
                unsigned bh[4], bo[4];
                int n = wn * 64 + ng * 16 + (t8 & 1) * 8 + r8;
                ldm4(bh, sb + BHI(s) + n * RS + u * 16);
                ldm4(bo, sb + BLO(s) + n * RS + u * 16);
#pragma unroll
                for (int mi = 0; mi < 2; mi++)
#pragma unroll
                    for (int o = 0; o < 2; o++) {
                        float (&A_)[4] = acc[mi][ng * 2 + o];
                        mma16816(A_, ah[mi], bh[o], bh[o + 2]);
                        mma16816(A_, ah[mi], bo[o], bo[o + 2]);
                        mma16816(A_, al[mi], bh[o], bh[o + 2]);
                    }
            }
        }
        CP_WAIT0();
        __syncthreads();
    }

    const int rq = lane >> 2, cq = (lane & 3) * 2;
#pragma unroll
    for (int mi = 0; mi < 2; mi++)
#pragma unroll
        for (int nj = 0; nj < 8; nj++) {
            const int colg = wn * 64 + nj * 8 + cq;
            const float bb0 = __ldg(b2v + colg), bb1 = __ldg(b2v + colg + 1);
#pragma unroll
            for (int hr = 0; hr < 2; hr++) {
                const int r = wm * 32 + mi * 16 + rq + hr * 8;
                float2 v = make_float2(acc[mi][nj][hr * 2 + 0] + bb0,
                                       acc[mi][nj][hr * 2 + 1] + bb1);
                *(float2*)(g_gf + (row0 + r) * HID + colg) = v;
            }
        }
}

// ---------- solve: 32 rows/block, warp-per-row SPD solve + Wl epilogue ------
__global__ __launch_bounds__(256)
void solve_k(const float* __restrict__ t, const float* __restrict__ Wl,
             const float* __restrict__ bl, float* __restrict__ out)
{
    __shared__ float Asm[8][16 * 17];
    __shared__ float Gsm[8][16 * 17];
    __shared__ float ysm[32][MD];
    const int tid = threadIdx.x, w = tid >> 5, lane = tid & 31;
    const size_t row0 = (size_t)blockIdx.x * 32;

    for (int ii = 0; ii < 4; ii++) {
        const int r = w * 4 + ii;
        const size_t grow = row0 + r;
        const float* gfr = g_gf + grow * HID;
        for (int p = lane; p < 256; p += 32) Asm[w][(p >> 4) * 17 + (p & 15)] = gfr[p];
        if (lane < MD)
            ysm[r][lane] = -__ldg(g_xi + grow * MD + lane) / (__ldg(t + grow) + 1e-6f);
        __syncwarp();
        for (int p = lane; p < 256; p += 32) {
            const int i = p >> 4, j = p & 15;
            float s = (i == j) ? 0.1f : 0.0f;
#pragma unroll
            for (int k = 0; k < MD; k++) s += Asm[w][i * 17 + k] * Asm[w][j * 17 + k];
            Gsm[w][i * 17 + j] = s;
        }
        __syncwarp();
        for (int k = 0; k < MD; k++) {
            const float piv = Gsm[w][k * 17 + k];
            const int i = k + 1 + lane;
            if (i < MD) {
                const float f = Gsm[w][i * 17 + k] / piv;
                for (int c2 = k; c2 < MD; c2++) Gsm[w][i * 17 + c2] -= f * Gsm[w][k * 17 + c2];
                ysm[r][i] -= f * ysm[r][k];
            }
            __syncwarp();
        }
        if (lane == 0) {
            for (int k = MD - 1; k >= 0; k--) {
                float s = ysm[r][k];
                for (int c2 = k + 1; c2 < MD; c2++) s -= Gsm[w][k * 17 + c2] * ysm[r][c2];
                ysm[r][k] = s / Gsm[w][k * 17 + k];
            }
        }
        __syncwarp();
    }
    __syncthreads();

    for (int it = 0; it < 4; it++) {
        const int col = tid + it * 256;
        if (col < DD) {
            float wv[MD];
#pragma unroll
            for (int k = 0; k < MD; k++) wv[k] = __ldg(Wl + (size_t)k * DD + col);
            const float bb = __ldg(bl + col);
            for (int r2 = 0; r2 < 32; r2++) {
                float s = bb;
#pragma unroll
                for (int k = 0; k < MD; k++) s += ysm[r2][k] * wv[k];
                out[(row0 + r2) * DD + col] = s;
            }
        }
    }
}

extern "C" void kernel_launch(void* const* d_in, const int* in_sizes, int n_in,
                              void* d_out, int out_size)
{
    const float* x_t = (const float*)d_in[0];
    const float* t   = (const float*)d_in[1];
    const float* W1  = (const float*)d_in[2];
    const float* b1  = (const float*)d_in[3];
    const float* W2  = (const float*)d_in[4];
    const float* b2  = (const float*)d_in[5];
    const float* Wp  = (const float*)d_in[6];
    const float* bp  = (const float*)d_in[7];
    const float* Wl  = (const float*)d_in[8];
    const float* bl  = (const float*)d_in[9];
    float* out = (float*)d_out;

    cudaFuncSetAttribute((const void*)gemm1_m, cudaFuncAttributeMaxDynamicSharedMemorySize, SMG1);
    cudaFuncSetAttribute((const void*)gemm2_m, cudaFuncAttributeMaxDynamicSharedMemorySize, SMG2);

    prep_kernel<<<1140, 256>>>(W1, W2, Wp);
    gemm1_m<<<B_ / 64, 256, SMG1>>>(x_t, b1, bp);
    gemm2_m<<<B_ / 64, 256, SMG2>>>(b2);
    solve_k<<<B_ / 32, 256>>>(t, Wl, bl, out);
}

// round 8
// speedup vs baseline: 1.2012x; 1.2012x over previous
#include <cuda_runtime.h>
#include <cuda_fp16.h>

#define B_  131072
#define DD  784
#define HID 256
#define MD  16
#define RS  80   // padded smem row stride (bytes) for a 32-half k-row

__device__ __align__(16) __half g_W1t_hi[HID * 832];
__device__ __align__(16) __half g_W1t_lo[HID * 832];
__device__ __align__(16) __half g_W2t_hi[HID * HID];
__device__ __align__(16) __half g_W2t_lo[HID * HID];
__device__ __align__(16) __half g_Wpt_hi[MD * 832];
__device__ __align__(16) __half g_Wpt_lo[MD * 832];
__device__ __align__(16) __half g_h_hi[(size_t)B_ * HID];
__device__ __align__(16) __half g_h_lo[(size_t)B_ * HID];
__device__ __align__(16) float g_gf[(size_t)B_ * HID];
__device__ __align__(16) float g_xi[(size_t)B_ * MD];

__device__ __forceinline__ unsigned su32(const void* p) {
    unsigned a;
    asm("{ .reg .u64 t; cvta.to.shared.u64 t, %1; cvt.u32.u64 %0, t; }" : "=r"(a) : "l"(p));
    return a;
}
__device__ __forceinline__ void ldm4(unsigned (&r)[4], unsigned addr) {
    asm volatile("ldmatrix.sync.aligned.m8n8.x4.shared.b16 {%0,%1,%2,%3}, [%4];"
                 : "=r"(r[0]), "=r"(r[1]), "=r"(r[2]), "=r"(r[3]) : "r"(addr));
}
__device__ __forceinline__ void mma16816(float (&c)[4], const unsigned (&a)[4],
                                         unsigned b0, unsigned b1) {
    asm volatile("mma.sync.aligned.m16n8k16.row.col.f32.f16.f16.f32 "
                 "{%0,%1,%2,%3}, {%4,%5,%6,%7}, {%8,%9}, {%0,%1,%2,%3};"
                 : "+f"(c[0]), "+f"(c[1]), "+f"(c[2]), "+f"(c[3])
                 : "r"(a[0]), "r"(a[1]), "r"(a[2]), "r"(a[3]), "r"(b0), "r"(b1));
}
__device__ __forceinline__ void cpa16(unsigned s, const void* g) {
    asm volatile("cp.async.cg.shared.global [%0], [%1], 16;" :: "r"(s), "l"(g));
}
#define CP_COMMIT() asm volatile("cp.async.commit_group;" ::: "memory")
#define CP_WAIT0()  asm volatile("cp.async.wait_group 0;" ::: "memory")

__device__ __forceinline__ unsigned pk(__half a, __half b) {
    return (unsigned)__half_as_ushort(a) | ((unsigned)__half_as_ushort(b) << 16);
}
__device__ __forceinline__ void split(float v, __half& h, __half& l) {
    h = __float2half_rn(v);
    l = __float2half_rn(v - __half2float(h));
}

// prep: plain transposed row-major [n][k] fp16 hi/lo, zero-padded K
__global__ void prep_kernel(const float* __restrict__ W1, const float* __restrict__ W2,
                            const float* __restrict__ Wp) {
    int idx = blockIdx.x * 256 + threadIdx.x;
    const int T1 = HID * 832, T2 = HID * HID, T3 = MD * 832;
    if (idx < T1) {
        int n = idx / 832, k = idx - n * 832;
        float v = (k < DD) ? W1[(size_t)k * HID + n] : 0.0f;
        __half h, l; split(v, h, l);
        g_W1t_hi[idx] = h; g_W1t_lo[idx] = l;
    } else if (idx < T1 + T2) {
        int j = idx - T1, n = j >> 8, k = j & 255;
        float v = W2[(size_t)k * HID + n];
        __half h, l; split(v, h, l);
        g_W2t_hi[j] = h; g_W2t_lo[j] = l;
    } else if (idx < T1 + T2 + T3) {
        int j = idx - T1 - T2, n = j / 832, k = j - n * 832;
        float v = (k < DD) ? Wp[(size_t)k * MD + n] : 0.0f;
        __half h, l; split(v, h, l);
        g_Wpt_hi[j] = h; g_Wpt_lo[j] = l;
    }
}

// smem layout per stage (51200 B): A hi 5120 | A lo 5120 | B hi 20480 | B lo 20480
#define AHI(s) ((s) * 51200)
#define ALO(s) ((s) * 51200 + 5120)
#define BHI(s) ((s) * 51200 + 10240)
#define BLO(s) ((s) * 51200 + 30720)
#define PHI(s) (102400 + (s) * 2560)
#define PLO(s) (102400 + (s) * 2560 + 1280)
#define SMG1 107520
#define SMG2 102400

// ---------- GEMM1 merged: h = relu(x@W1+b1), xi = x@Wp+bp. M64 N256 k32 -----
__global__ __launch_bounds__(256, 2)
void gemm1_m(const float* __restrict__ X, const float* __restrict__ b1v,
             const float* __restrict__ bpv) {
    extern __shared__ char smc[];
    const unsigned sb = su32(smc);
    const int tid = threadIdx.x, lane = tid & 31, w = tid >> 5;
    const int wm = w >> 2, wn = w & 3;
    const int t8 = lane >> 3, r8 = lane & 7;
    const size_t row0 = (size_t)blockIdx.x * 64;

    float acc[2][8][4] = {};
    float axi[2][2][4] = {};
    float xr[8];
    const int ar = tid >> 2, av = tid & 3;

    auto ldgA = [&](int c) {
        int col = c * 32 + av * 8;
        if (col < DD) {
            *(float4*)xr       = *(const float4*)(X + (row0 + ar) * DD + col);
            *(float4*)(xr + 4) = *(const float4*)(X + (row0 + ar) * DD + col + 4);
        } else {
#pragma unroll
            for (int i = 0; i < 8; i++) xr[i] = 0.0f;
        }
    };
    auto stsA = [&](int s) {
        __half h[8], l[8];
#pragma unroll
        for (int i = 0; i < 8; i++) split(xr[i], h[i], l[i]);
        uint4 vh, vl;
        vh.x = pk(h[0], h[1]); vh.y = pk(h[2], h[3]); vh.z = pk(h[4], h[5]); vh.w = pk(h[6], h[7]);
        vl.x = pk(l[0], l[1]); vl.y = pk(l[2], l[3]); vl.z = pk(l[4], l[5]); vl.w = pk(l[6], l[7]);
        *(uint4*)(smc + AHI(s) + ar * RS + av * 16) = vh;
        *(uint4*)(smc + ALO(s) + ar * RS + av * 16) = vl;
    };
    auto cpaB = [&](int c, int s) {
#pragma unroll
        for (int i = 0; i < 4; i++) {
            int j = tid + i * 256, r = j >> 2, v = j & 3;
            const size_t src = (size_t)r * 832 + c * 32 + v * 8;
            cpa16(sb + BHI(s) + r * RS + v * 16, g_W1t_hi + src);
            cpa16(sb + BLO(s) + r * RS + v * 16, g_W1t_lo + src);
        }
        if (tid < 128) {
            int r = (tid & 63) >> 2, v = tid & 3;
            const size_t src = (size_t)r * 832 + c * 32 + v * 8;
            if (tid < 64) cpa16(sb + PHI(s) + r * RS + v * 16, g_Wpt_hi + src);
            else          cpa16(sb + PLO(s) + r * RS + v * 16, g_Wpt_lo + src);
        }
    };

    ldgA(0); stsA(0); cpaB(0, 0);
    CP_COMMIT(); CP_WAIT0();
    __syncthreads();

    for (int c = 0; c < 26; c++) {
        const int s = c & 1;
        const bool more = (c + 1 < 26);
        if (more) { ldgA(c + 1); cpaB(c + 1, s ^ 1); CP_COMMIT(); }
#pragma unroll
        for (int ks = 0; ks < 2; ks++) {
            const int u = ks * 2 + (t8 >> 1);
            unsigned ah[2][4], al[2][4];
#pragma unroll
            for (int mi = 0; mi < 2; mi++) {
                int m = wm * 32 + mi * 16 + (t8 & 1) * 8 + r8;
                ldm4(ah[mi], sb + AHI(s) + m * RS + u * 16);
                ldm4(al[mi], sb + ALO(s) + m * RS + u * 16);
            }
#pragma unroll
            for (int ng = 0; ng < 4; ng++) {
                unsigned bh[4], bo[4];
                int n = wn * 64 + ng * 16 + (t8 & 1) * 8 + r8;
                ldm4(bh, sb + BHI(s) + n * RS + u * 16);
                ldm4(bo, sb + BLO(s) + n * RS + u * 16);
#pragma unroll
                for (int mi = 0; mi < 2; mi++)
#pragma unroll
                    for (int o = 0; o < 2; o++) {
                        float (&A_)[4] = acc[mi][ng * 2 + o];
                        mma16816(A_, ah[mi], bh[o], bh[o + 2]);
                        mma16816(A_, ah[mi], bo[o], bo[o + 2]);
                        mma16816(A_, al[mi], bh[o], bh[o + 2]);
                    }
            }
            if (wn == 0) {
                unsigned ph[4], po[4];
                int n = (t8 & 1) * 8 + r8;
                ldm4(ph, sb + PHI(s) + n * RS + u * 16);
                ldm4(po, sb + PLO(s) + n * RS + u * 16);
#pragma unroll
                for (int mi = 0; mi < 2; mi++)
#pragma unroll
                    for (int nj = 0; nj < 2; nj++) {
                        mma16816(axi[mi][nj], ah[mi], ph[nj], ph[nj + 2]);
                        mma16816(axi[mi][nj], ah[mi], po[nj], po[nj + 2]);
                        mma16816(axi[mi][nj], al[mi], ph[nj], ph[nj + 2]);
                    }
            }
        }
        if (more) stsA(s ^ 1);
        CP_WAIT0();
        __syncthreads();
    }

    const int rq = lane >> 2, cq = (lane & 3) * 2;
#pragma unroll
    for (int mi = 0; mi < 2; mi++)
#pragma unroll
        for (int nj = 0; nj < 8; nj++) {
            const int colg = wn * 64 + nj * 8 + cq;
            const float bb0 = __ldg(b1v + colg), bb1 = __ldg(b1v + colg + 1);
#pragma unroll
            for (int hr = 0; hr < 2; hr++) {
                const int r = wm * 32 + mi * 16 + rq + hr * 8;
                float v0 = fmaxf(acc[mi][nj][hr * 2 + 0] + bb0, 0.0f);
                float v1 = fmaxf(acc[mi][nj][hr * 2 + 1] + bb1, 0.0f);
                __half h0, l0, h1, l1;
                split(v0, h0, l0); split(v1, h1, l1);
                const size_t gi = (row0 + r) * HID + colg;
                *(unsigned*)(g_h_hi + gi) = pk(h0, h1);
                *(unsigned*)(g_h_lo + gi) = pk(l0, l1);
            }
        }
    if (wn == 0) {
#pragma unroll
        for (int mi = 0; mi < 2; mi++)
#pragma unroll
            for (int nj = 0; nj < 2; nj++) {
                const int colg = nj * 8 + cq;
                const float bb0 = __ldg(bpv + colg), bb1 = __ldg(bpv + colg + 1);
#pragma unroll
                for (int hr = 0; hr < 2; hr++) {
                    const int r = wm * 32 + mi * 16 + rq + hr * 8;
                    float2 v = make_float2(axi[mi][nj][hr * 2 + 0] + bb0,
                                           axi[mi][nj][hr * 2 + 1] + bb1);
                    *(float2*)(g_xi + (row0 + r) * MD + colg) = v;
                }
            }
    }
}

// ---------- GEMM2 merged: gf = h@W2+b2. M64 N256 k32 -----------------------
__global__ __launch_bounds__(256, 2)
void gemm2_m(const float* __restrict__ b2v) {
    extern __shared__ char smc[];
    const unsigned sb = su32(smc);
    const int tid = threadIdx.x, lane = tid & 31, w = tid >> 5;
    const int wm = w >> 2, wn = w & 3;
    const int t8 = lane >> 3, r8 = lane & 7;
    const size_t row0 = (size_t)blockIdx.x * 64;

    float acc[2][8][4] = {};

    auto cpaA = [&](int c, int s) {
        int r = tid >> 2, v = tid & 3;
        const size_t src = (row0 + r) * HID + c * 32 + v * 8;
        cpa16(sb + AHI(s) + r * RS + v * 16, g_h_hi + src);
        cpa16(sb + ALO(s) + r * RS + v * 16, g_h_lo + src);
    };
    auto cpaB = [&](int c, int s) {
#pragma unroll
        for (int i = 0; i < 4; i++) {
            int j = tid + i * 256, r = j >> 2, v = j & 3;
            const size_t src = (size_t)r * HID + c * 32 + v * 8;
            cpa16(sb + BHI(s) + r * RS + v * 16, g_W2t_hi + src);
            cpa16(sb + BLO(s) + r * RS + v * 16, g_W2t_lo + src);
        }
    };

    cpaA(0, 0); cpaB(0, 0);
    CP_COMMIT(); CP_WAIT0();
    __syncthreads();

    for (int c = 0; c < 8; c++) {
        const int s = c & 1;
        const bool more = (c + 1 < 8);
        if (more) { cpaA(c + 1, s ^ 1); cpaB(c + 1, s ^ 1); CP_COMMIT(); }
#pragma unroll
        for (int ks = 0; ks < 2; ks++) {
            const int u = ks * 2 + (t8 >> 1);
            unsigned ah[2][4], al[2][4];
#pragma unroll
            for (int mi = 0; mi < 2; mi++) {
                int m = wm * 32 + mi * 16 + (t8 & 1) * 8 + r8;
                ldm4(ah[mi], sb + AHI(s) + m * RS + u * 16);
                ldm4(al[mi], sb + ALO(s) + m * RS + u * 16);
            }
#pragma unroll
            for (int ng = 0; ng < 4; ng++) {
                unsigned bh[4], bo[4];
                int n = wn * 64 + ng * 16 + (t8 & 1) * 8 + r8;
                ldm4(bh, sb + BHI(s) + n * RS + u * 16);
                ldm4(bo, sb + BLO(s) + n * RS + u * 16);
#pragma unroll
                for (int mi = 0; mi < 2; mi++)
#pragma unroll
                    for (int o = 0; o < 2; o++) {
                        float (&A_)[4] = acc[mi][ng * 2 + o];
                        mma16816(A_, ah[mi], bh[o], bh[o + 2]);
                        mma16816(A_, ah[mi], bo[o], bo[o + 2]);
                        mma16816(A_, al[mi], bh[o], bh[o + 2]);
                    }
            }
        }
        CP_WAIT0();
        __syncthreads();
    }

    const int rq = lane >> 2, cq = (lane & 3) * 2;
#pragma unroll
    for (int mi = 0; mi < 2; mi++)
#pragma unroll
        for (int nj = 0; nj < 8; nj++) {
            const int colg = wn * 64 + nj * 8 + cq;
            const float bb0 = __ldg(b2v + colg), bb1 = __ldg(b2v + colg + 1);
#pragma unroll
            for (int hr = 0; hr < 2; hr++) {
                const int r = wm * 32 + mi * 16 + rq + hr * 8;
                float2 v = make_float2(acc[mi][nj][hr * 2 + 0] + bb0,
                                       acc[mi][nj][hr * 2 + 1] + bb1);
                *(float2*)(g_gf + (row0 + r) * HID + colg) = v;
            }
        }
}

// ---------- solve: register-resident AA^T + Gauss-Jordan via shuffles -------
// Warp handles 2 rows per pass (lanes 0-15 / 16-31), 4 rows total; block = 32 rows.
__global__ __launch_bounds__(256)
void solve_k(const float* __restrict__ t, const float* __restrict__ Wl,
             const float* __restrict__ bl, float* __restrict__ out)
{
    __shared__ float ysm[32][17];
    const int tid = threadIdx.x, w = tid >> 5, lane = tid & 31;
    const int sl = lane & 15;          // matrix row index
    const int half = lane >> 4;        // which of the 2 rows this half-warp owns
    const size_t row0 = (size_t)blockIdx.x * 32;

    for (int pass = 0; pass < 2; pass++) {
        const int r = w * 4 + pass * 2 + half;
        const size_t grow = row0 + r;

        // load A row sl (16 floats) straight into registers
        float a[16];
        const float4* ap = (const float4*)(g_gf + grow * HID + sl * 16);
        float4 q0 = ap[0], q1 = ap[1], q2 = ap[2], q3 = ap[3];
        a[0]=q0.x; a[1]=q0.y; a[2]=q0.z; a[3]=q0.w;
        a[4]=q1.x; a[5]=q1.y; a[6]=q1.z; a[7]=q1.w;
        a[8]=q2.x; a[9]=q2.y; a[10]=q2.z; a[11]=q2.w;
        a[12]=q3.x; a[13]=q3.y; a[14]=q3.z; a[15]=q3.w;

        // g[sl][j] = 0.1*delta + sum_k a[sl][k] * a[j][k]   (width-16 shuffles)
        float g[16];
#pragma unroll
        for (int j = 0; j < 16; j++) {
            float s = (sl == j) ? 0.1f : 0.0f;
#pragma unroll
            for (int k = 0; k < 16; k++)
                s += a[k] * __shfl_sync(0xffffffffu, a[k], j, 16);
            g[j] = s;
        }

        float y = -__ldg(g_xi + grow * MD + sl) / (__ldg(t + grow) + 1e-6f);

        // Gauss-Jordan, full elimination; pivot at step k is the final diagonal
        float diag = 1.0f;
#pragma unroll
        for (int k = 0; k < 16; k++) {
            const float piv = __shfl_sync(0xffffffffu, g[k], k, 16);
            const float yk  = __shfl_sync(0xffffffffu, y, k, 16);
            const float f   = g[k] / piv;
            if (sl == k) diag = piv;
#pragma unroll
            for (int c = 0; c < 16; c++) {
                const float rkc = __shfl_sync(0xffffffffu, g[c], k, 16);
                if (sl != k) g[c] -= f * rkc;
            }
            if (sl != k) y -= f * yk;
        }
        ysm[r][sl] = y / diag;
    }
    __syncthreads();

    // out = y @ Wl + bl for the block's 32 rows
    for (int it = 0; it < 4; it++) {
        const int col = tid + it * 256;
        if (col < DD) {
            float wv[MD];
#pragma unroll
            for (int k = 0; k < MD; k++) wv[k] = __ldg(Wl + (size_t)k * DD + col);
            const float bb = __ldg(bl + col);
            for (int r2 = 0; r2 < 32; r2++) {
                float s = bb;
#pragma unroll
                for (int k = 0; k < MD; k++) s += ysm[r2][k] * wv[k];
                out[(row0 + r2) * DD + col] = s;
            }
        }
    }
}

extern "C" void kernel_launch(void* const* d_in, const int* in_sizes, int n_in,
                              void* d_out, int out_size)
{
    const float* x_t = (const float*)d_in[0];
    const float* t   = (const float*)d_in[1];
    const float* W1  = (const float*)d_in[2];
    const float* b1  = (const float*)d_in[3];
    const float* W2  = (const float*)d_in[4];
    const float* b2  = (const float*)d_in[5];
    const float* Wp  = (const float*)d_in[6];
    const float* bp  = (const float*)d_in[7];
    const float* Wl  = (const float*)d_in[8];
    const float* bl  = (const float*)d_in[9];
    float* out = (float*)d_out;

    cudaFuncSetAttribute((const void*)gemm1_m, cudaFuncAttributeMaxDynamicSharedMemorySize, SMG1);
    cudaFuncSetAttribute((const void*)gemm2_m, cudaFuncAttributeMaxDynamicSharedMemorySize, SMG2);

    prep_kernel<<<1140, 256>>>(W1, W2, Wp);
    gemm1_m<<<B_ / 64, 256, SMG1>>>(x_t, b1, bp);
    gemm2_m<<<B_ / 64, 256, SMG2>>>(b2);
    solve_k<<<B_ / 32, 256>>>(t, Wl, bl, out);
}